// round 14
// baseline (speedup 1.0000x reference)
#include <cuda_runtime.h>
#include <cuda_bf16.h>
#include <math.h>
#include <stdint.h>

// Problem constants
#define BB 128
#define NN 64
#define DD 768
#define HH 32
#define DKK 24
#define LL 4
#define TEE 32
#define TDD 40
#define VPP 512
#define NQKV 2304   // 3*H*DK

// ---------------- scratch (device globals; no dynamic alloc) ----------------
__device__ float g_qkv[BB * NN * NQKV];            // [8192, 2304] f32
__device__ float g_pb [BB * HH * NN * NN];         // path bias [b,h,i,j]
__device__ __nv_bfloat16 g_Ah[BB * NN * DD];       // A hi  [8192,768]
__device__ __nv_bfloat16 g_Al[BB * NN * DD];       // A lo
__device__ __nv_bfloat16 g_Bh[NQKV * DD];          // B hi  [N,K]
__device__ __nv_bfloat16 g_Bl[NQKV * DD];          // B lo

// ======================= PTX helpers (base-target safe) =====================
__device__ __forceinline__ uint32_t smem_u32(const void* p) {
    uint32_t a;
    asm("{ .reg .u64 t; cvta.to.shared.u64 t, %1; cvt.u32.u64 %0, t; }" : "=r"(a) : "l"(p));
    return a;
}

#define CPASYNC16(dst, src) \
    asm volatile("cp.async.cg.shared.global [%0], [%1], 16;" :: "r"(dst), "l"(src) : "memory")
#define CPCOMMIT() asm volatile("cp.async.commit_group;" ::: "memory")
#define CPWAIT1()  asm volatile("cp.async.wait_group 1;" ::: "memory")

#define LDMX4(r0, r1, r2, r3, addr) \
    asm volatile("ldmatrix.sync.aligned.m8n8.x4.shared.b16 {%0,%1,%2,%3}, [%4];" \
        : "=r"(r0), "=r"(r1), "=r"(r2), "=r"(r3) : "r"(addr))

#define MMA16816(d, a, b0, b1) \
    asm volatile("mma.sync.aligned.m16n8k16.row.col.f32.bf16.bf16.f32 " \
        "{%0,%1,%2,%3}, {%4,%5,%6,%7}, {%8,%9}, {%0,%1,%2,%3};" \
        : "+f"((d)[0]), "+f"((d)[1]), "+f"((d)[2]), "+f"((d)[3]) \
        : "r"((a)[0]), "r"((a)[1]), "r"((a)[2]), "r"((a)[3]), "r"(b0), "r"(b1))

// ======================= prep kernels =======================================
__global__ void __launch_bounds__(256) ksplit(const float* __restrict__ X,
                                              __nv_bfloat16* __restrict__ H,
                                              __nv_bfloat16* __restrict__ L, int n)
{
    int i = (blockIdx.x * 256 + threadIdx.x) * 4;
    if (i >= n) return;
    float4 v = *(const float4*)(X + i);
    __nv_bfloat16 h0 = __float2bfloat16(v.x), h1 = __float2bfloat16(v.y);
    __nv_bfloat16 h2 = __float2bfloat16(v.z), h3 = __float2bfloat16(v.w);
    __nv_bfloat16 l0 = __float2bfloat16(v.x - __bfloat162float(h0));
    __nv_bfloat16 l1 = __float2bfloat16(v.y - __bfloat162float(h1));
    __nv_bfloat16 l2 = __float2bfloat16(v.z - __bfloat162float(h2));
    __nv_bfloat16 l3 = __float2bfloat16(v.w - __bfloat162float(h3));
    ((__nv_bfloat162*)(H + i))[0] = __nv_bfloat162(h0, h1);
    ((__nv_bfloat162*)(H + i))[1] = __nv_bfloat162(h2, h3);
    ((__nv_bfloat162*)(L + i))[0] = __nv_bfloat162(l0, l1);
    ((__nv_bfloat162*)(L + i))[1] = __nv_bfloat162(l2, l3);
}

// W[K,N] f32 -> H,L [N,K] bf16 (transpose + split)
__global__ void __launch_bounds__(256) ksplitT(const float* __restrict__ W,
                                               __nv_bfloat16* __restrict__ H,
                                               __nv_bfloat16* __restrict__ L,
                                               int K, int N)
{
    __shared__ float t[32][33];
    int n0 = blockIdx.x * 32, k0 = blockIdx.y * 32;
    int tx = threadIdx.x, ty = threadIdx.y;
    #pragma unroll
    for (int r = ty; r < 32; r += 8)
        t[r][tx] = W[(long)(k0 + r) * N + n0 + tx];
    __syncthreads();
    #pragma unroll
    for (int r = ty; r < 32; r += 8) {
        float v = t[tx][r];
        __nv_bfloat16 h = __float2bfloat16(v);
        __nv_bfloat16 l = __float2bfloat16(v - __bfloat162float(h));
        long o = (long)(n0 + r) * K + k0 + tx;
        H[o] = h;
        L[o] = l;
    }
}

// ======================= path-bias precompute ===============================
__global__ void __launch_bounds__(256) pb_kernel(
    const int* __restrict__ traj, const int* __restrict__ distance,
    const float* __restrict__ path_emb, const float* __restrict__ path_pos,
    float* __restrict__ pb_out)
{
    __shared__ __align__(16) int stg[8][200];
    __shared__ __align__(16) float tile[32][132];
    const int tid = threadIdx.x, w = tid >> 5, lane = tid & 31;
    const long e0 = (long)blockIdx.x * 128;
    const int we0 = w * 16;

    float wl[4];
    #pragma unroll
    for (int l = 0; l < 4; l++) wl[l] = path_pos[l * HH + lane];

    const int4* src = (const int4*)(traj + (e0 + we0) * 12);
    ((int4*)stg[w])[lane] = src[lane];
    if (lane < 16) ((int4*)stg[w])[32 + lane] = src[32 + lane];
    int ddv = 0;
    if (lane < 16) ddv = distance[e0 + we0 + lane];
    __syncwarp();

    #pragma unroll 4
    for (int k = 0; k < 16; k++) {
        int dd = __shfl_sync(0xffffffffu, ddv, k);
        const int* tj = &stg[w][k * 12];
        float acc = 0.f;
        #pragma unroll
        for (int l = 0; l < 4; l++) {
            float s3 = path_emb[tj[3 * l + 0] * HH + lane]
                     + path_emb[tj[3 * l + 1] * HH + lane]
                     + path_emb[tj[3 * l + 2] * HH + lane];
            acc += wl[l] * s3;
        }
        tile[lane][we0 + k] = acc * __frcp_rn(fmaxf((float)dd, 1.f));
    }
    __syncthreads();

    const int row = tid >> 3;
    const int c0 = (tid & 7) * 16;
    const long b = e0 >> 12;
    const long ijo = e0 & 4095;
    float* orow = pb_out + ((b * HH + row) << 12) + ijo;
    #pragma unroll
    for (int k2 = 0; k2 < 4; k2++) {
        float4 v = *(float4*)&tile[row][c0 + k2 * 4];
        *(float4*)&orow[c0 + k2 * 4] = v;
    }
}

// ======================= mma.sync GEMM (bf16x3) =============================
// 128x128x32 tile, 8 warps, 3-stage cp.async pipeline, 1 barrier/iter.
// SMEM rows: 64B (32 bf16), XOR chunk swizzle chunk'=(chunk+(row>>1))&3.
// Prefetch issued AFTER kk=0 LDSM so MMAs start early each iteration.
#define GTILEB 8192                    // 128 rows * 64B
#define GM_STAGEB (4 * GTILEB)         // 32768 (Ah,Al,Bh,Bl)
#define GM_SMEM (3 * GM_STAGEB)        // 98304

__device__ __forceinline__ int swofs(int r, int ch) {
    return r * 64 + (((ch + (r >> 1)) & 3) << 4);
}

__global__ void __launch_bounds__(256) mma_gemm_kernel(
    const __nv_bfloat16* __restrict__ Ah, const __nv_bfloat16* __restrict__ Al,
    const __nv_bfloat16* __restrict__ Bh, const __nv_bfloat16* __restrict__ Bl,
    const float* __restrict__ bias, float* __restrict__ C, int Ncols)
{
    extern __shared__ char smem[];
    const uint32_t sb = smem_u32(smem);
    const int tid = threadIdx.x, wid = tid >> 5, lane = tid & 31;
    const int nT = blockIdx.x, mT = blockIdx.y;
    const int wm = wid >> 1;
    const int wn = wid & 1;

    const __nv_bfloat16* srcA_h = Ah + (long)(mT * 128) * DD;
    const __nv_bfloat16* srcA_l = Al + (long)(mT * 128) * DD;
    const __nv_bfloat16* srcB_h = Bh + (long)(nT * 128) * DD;
    const __nv_bfloat16* srcB_l = Bl + (long)(nT * 128) * DD;

    float acc[2][8][4];
    #pragma unroll
    for (int s = 0; s < 2; s++)
        #pragma unroll
        for (int f = 0; f < 8; f++)
            #pragma unroll
            for (int x = 0; x < 4; x++) acc[s][f][x] = 0.f;

    auto load_stage = [&](int st, int k0) {
        uint32_t sbase = sb + st * GM_STAGEB;
        #pragma unroll
        for (int i = 0; i < 8; i++) {
            int idx = ((i & 1) << 8) + tid;
            int row = idx >> 2, ch = idx & 3;
            const __nv_bfloat16* src;
            switch (i >> 1) {
                case 0: src = srcA_h; break;
                case 1: src = srcA_l; break;
                case 2: src = srcB_h; break;
                default: src = srcB_l; break;
            }
            src += (long)row * DD + k0 + ch * 8;
            uint32_t dst = sbase + (i >> 1) * GTILEB + swofs(row, ch);
            CPASYNC16(dst, src);
        }
        CPCOMMIT();
    };

    load_stage(0, 0);
    load_stage(1, 32);

    const int arow = wm * 32 + (lane & 15);
    const int chq = lane >> 4;                     // 0 or 1

    for (int c = 0; c < 24; c++) {
        CPWAIT1();
        __syncthreads();

        uint32_t st = sb + (c % 3) * GM_STAGEB;
        uint32_t sAh = st, sAl = st + GTILEB, sBh = st + 2 * GTILEB, sBl = st + 3 * GTILEB;

        // ---- kk = 0: LDSM first, then prefetch under MMA shadow ----
        {
            const int ch = chq;
            uint32_t ah[2][4], al[2][4], bh[4][4], bl[4][4];
            LDMX4(ah[0][0], ah[0][1], ah[0][2], ah[0][3], sAh + swofs(arow, ch));
            LDMX4(ah[1][0], ah[1][1], ah[1][2], ah[1][3], sAh + swofs(arow + 16, ch));
            LDMX4(al[0][0], al[0][1], al[0][2], al[0][3], sAl + swofs(arow, ch));
            LDMX4(al[1][0], al[1][1], al[1][2], al[1][3], sAl + swofs(arow + 16, ch));
            #pragma unroll
            for (int g = 0; g < 4; g++) {
                int brow = wn * 64 + g * 16 + (lane & 15);
                LDMX4(bh[g][0], bh[g][1], bh[g][2], bh[g][3], sBh + swofs(brow, ch));
                LDMX4(bl[g][0], bl[g][1], bl[g][2], bl[g][3], sBl + swofs(brow, ch));
            }
            if (c + 2 < 24) load_stage((c + 2) % 3, (c + 2) * 32);
            else CPCOMMIT();                        // keep wait depth uniform
            #pragma unroll
            for (int s = 0; s < 2; s++)
                #pragma unroll
                for (int f = 0; f < 8; f++) {
                    int g = f >> 1, p = f & 1;
                    MMA16816(acc[s][f], ah[s], bh[g][p], bh[g][p + 2]);
                    MMA16816(acc[s][f], ah[s], bl[g][p], bl[g][p + 2]);
                    MMA16816(acc[s][f], al[s], bh[g][p], bh[g][p + 2]);
                }
        }
        // ---- kk = 1 ----
        {
            const int ch = 2 + chq;
            uint32_t ah[2][4], al[2][4], bh[4][4], bl[4][4];
            LDMX4(ah[0][0], ah[0][1], ah[0][2], ah[0][3], sAh + swofs(arow, ch));
            LDMX4(ah[1][0], ah[1][1], ah[1][2], ah[1][3], sAh + swofs(arow + 16, ch));
            LDMX4(al[0][0], al[0][1], al[0][2], al[0][3], sAl + swofs(arow, ch));
            LDMX4(al[1][0], al[1][1], al[1][2], al[1][3], sAl + swofs(arow + 16, ch));
            #pragma unroll
            for (int g = 0; g < 4; g++) {
                int brow = wn * 64 + g * 16 + (lane & 15);
                LDMX4(bh[g][0], bh[g][1], bh[g][2], bh[g][3], sBh + swofs(brow, ch));
                LDMX4(bl[g][0], bl[g][1], bl[g][2], bl[g][3], sBl + swofs(brow, ch));
            }
            #pragma unroll
            for (int s = 0; s < 2; s++)
                #pragma unroll
                for (int f = 0; f < 8; f++) {
                    int g = f >> 1, p = f & 1;
                    MMA16816(acc[s][f], ah[s], bh[g][p], bh[g][p + 2]);
                    MMA16816(acc[s][f], ah[s], bl[g][p], bl[g][p + 2]);
                    MMA16816(acc[s][f], al[s], bh[g][p], bh[g][p + 2]);
                }
        }
    }

    #pragma unroll
    for (int s = 0; s < 2; s++) {
        int r0 = mT * 128 + wm * 32 + s * 16 + (lane >> 2);
        #pragma unroll
        for (int f = 0; f < 8; f++) {
            int col = nT * 128 + wn * 64 + f * 8 + (lane & 3) * 2;
            float b0 = bias[col], b1 = bias[col + 1];
            float2 v0 = make_float2(acc[s][f][0] + b0, acc[s][f][1] + b1);
            float2 v1 = make_float2(acc[s][f][2] + b0, acc[s][f][3] + b1);
            *(float2*)&C[(long)r0 * Ncols + col] = v0;
            *(float2*)&C[(long)(r0 + 8) * Ncols + col] = v1;
        }
    }
}

// ---------------- fused attention: one CTA per (b,h) ------------------------
#define OFF_SQ   0
#define OFF_SK   1600
#define OFF_SV   3200
#define OFF_QBE  4800
#define OFF_QBD  6848
#define OFF_KBE  9408
#define OFF_KBD  11456
#define OFF_VE   9408
#define OFF_VD   11456
#define OFF_SA   14016
#define OFF_EQE  14016
#define OFF_EKE  14816
#define OFF_EQD  15616
#define OFF_EKD  16616
#define OFF_STR  18176
#define OFF_STC  18240
#define OFF_SMB  18304
#define SMEM_FLOATS 18368
#define SMEM_BYTES  (SMEM_FLOATS * 4)   /* 73472 -> 3 CTAs/SM */

__global__ void __launch_bounds__(256, 3) attn_kernel(
    const float* __restrict__ qkv,
    const int* __restrict__ distance,
    const int* __restrict__ conn,
    const float* __restrict__ pb,
    const unsigned char* __restrict__ mask,
    const float* __restrict__ eq_t, const float* __restrict__ ek_t,
    const float* __restrict__ dq_t, const float* __restrict__ dk_t,
    const float* __restrict__ ev_t, const float* __restrict__ dv_t,
    const float* __restrict__ toep_r, const float* __restrict__ toep_c,
    __nv_bfloat16* __restrict__ zh, __nv_bfloat16* __restrict__ zl)
{
    extern __shared__ float sm[];
    float* sq  = sm + OFF_SQ;
    float* sk  = sm + OFF_SK;
    float* sv  = sm + OFF_SV;
    float* qbe = sm + OFF_QBE;
    float* qbd = sm + OFF_QBD;
    float* kbe = sm + OFF_KBE;
    float* kbd = sm + OFF_KBD;
    float* ve  = sm + OFF_VE;
    float* vd  = sm + OFF_VD;
    float* sa  = sm + OFF_SA;
    float* eqe = sm + OFF_EQE;
    float* eke = sm + OFF_EKE;
    float* eqd = sm + OFF_EQD;
    float* ekd = sm + OFF_EKD;
    float* str = sm + OFF_STR;
    float* stc = sm + OFF_STC;
    float* smb = sm + OFF_SMB;

    const int h = blockIdx.x;
    const int b = blockIdx.y;
    const int tid = threadIdx.x;
    const int warp = tid >> 5, lane = tid & 31;

    // ---- phase 1: loads ----
    for (int idx = tid; idx < NN * DKK; idx += 256) {
        int i = idx / DKK, d = idx % DKK;
        long base = (long)(b * NN + i) * NQKV + h * DKK + d;
        sq[i * 25 + d] = qkv[base];
        sk[i * 25 + d] = qkv[base + HH * DKK];
        sv[i * 25 + d] = qkv[base + 2 * HH * DKK];
    }
    for (int idx = tid; idx < TEE * DKK; idx += 256) {
        int t = idx / DKK, d = idx % DKK;
        long g = (long)(t * HH + h) * DKK + d;
        eqe[t * 25 + d] = eq_t[g];
        eke[t * 25 + d] = ek_t[g];
    }
    for (int idx = tid; idx < TDD * DKK; idx += 256) {
        int t = idx / DKK, d = idx % DKK;
        long g = (long)(t * HH + h) * DKK + d;
        eqd[t * 25 + d] = dq_t[g];
        ekd[t * 25 + d] = dk_t[g];
    }
    if (tid < NN) {
        str[tid] = toep_r[h * NN + tid];
        stc[tid] = toep_c[h * NN + tid];
        smb[tid] = mask[b * NN + tid] ? -1e30f : 0.f;
    }
    __syncthreads();

    // ---- phase 2a: qb tables (64x72 fused) ----
    {
        const int ip = tid >> 3, tg = tid & 7;
        const int i0 = ip * 2;
        float a0[9], a1[9];
        const float* tp[9];
        #pragma unroll
        for (int k = 0; k < 9; k++) {
            int t = tg * 9 + k;
            tp[k] = (t < TEE) ? (eke + t * 25) : (ekd + (t - TEE) * 25);
            a0[k] = 0.f; a1[k] = 0.f;
        }
        #pragma unroll 8
        for (int d = 0; d < DKK; d++) {
            float q0 = sq[i0 * 25 + d], q1 = sq[(i0 + 1) * 25 + d];
            #pragma unroll
            for (int k = 0; k < 9; k++) {
                float e = tp[k][d];
                a0[k] += q0 * e;
                a1[k] += q1 * e;
            }
        }
        #pragma unroll
        for (int k = 0; k < 9; k++) {
            int t = tg * 9 + k;
            if (t < TEE) {
                qbe[i0 * 32 + t] = a0[k];
                qbe[(i0 + 1) * 32 + t] = a1[k];
            } else {
                qbd[i0 * 40 + t - TEE] = a0[k];
                qbd[(i0 + 1) * 40 + t - TEE] = a1[k];
            }
        }
    }
    // ---- phase 2b: kb tables (72x64 fused) ----
    if (tid < 192) {
        const int tt = tid >> 3, jg = tid & 7;
        float ac[3][8];
        const float* ep[3];
        #pragma unroll
        for (int c = 0; c < 3; c++) {
            int t = tt * 3 + c;
            ep[c] = (t < TEE) ? (eqe + t * 25) : (eqd + (t - TEE) * 25);
            #pragma unroll
            for (int jj = 0; jj < 8; jj++) ac[c][jj] = 0.f;
        }
        #pragma unroll 8
        for (int d = 0; d < DKK; d++) {
            float e0 = ep[0][d], e1 = ep[1][d], e2 = ep[2][d];
            #pragma unroll
            for (int jj = 0; jj < 8; jj++) {
                float kv = sk[(jg + 8 * jj) * 25 + d];
                ac[0][jj] += e0 * kv;
                ac[1][jj] += e1 * kv;
                ac[2][jj] += e2 * kv;
            }
        }
        #pragma unroll
        for (int c = 0; c < 3; c++) {
            int t = tt * 3 + c;
            #pragma unroll
            for (int jj = 0; jj < 8; jj++) {
                int j = jg + 8 * jj;
                if (t < TEE) kbe[t * 64 + j] = ac[c][jj];
                else         kbd[(t - TEE) * 64 + j] = ac[c][jj];
            }
        }
    }
    __syncthreads();

    // ---- phase 3: gathers + path bias -> sa, (warp,lane) layout ------------
    const long base_bij = (long)b * (NN * NN);
    const float* pbh = pb + (((long)(b * HH + h)) << 12);
    unsigned int cd[8];
    #pragma unroll
    for (int r = 0; r < 8; r++) {
        int i = warp + 8 * r;
        int c0 = conn[base_bij + i * 64 + lane];
        int d0 = distance[base_bij + i * 64 + lane];
        int c1 = conn[base_bij + i * 64 + 32 + lane];
        int d1 = distance[base_bij + i * 64 + 32 + lane];
        cd[r] = (unsigned)c0 | ((unsigned)d0 << 8) | ((unsigned)c1 << 16) | ((unsigned)d1 << 24);
        sa[i * 65 + lane] = qbe[i * 32 + c0] + kbe[c0 * 64 + lane]
                          + qbd[i * 40 + d0] + kbd[d0 * 64 + lane]
                          + pbh[i * 64 + lane];
        sa[i * 65 + 32 + lane] = qbe[i * 32 + c1] + kbe[c1 * 64 + 32 + lane]
                               + qbd[i * 40 + d1] + kbd[d1 * 64 + 32 + lane]
                               + pbh[i * 64 + 32 + lane];
    }
    __syncthreads();

    // ---- phase 4: QK dot (4i x 4j tile); zero accumulators; load Ve/Vd -----
    const float scale = 0.2041241452319315f;
    {
        const int ti = tid >> 4, tj = tid & 15;
        float acc[4][4];
        #pragma unroll
        for (int ii = 0; ii < 4; ii++)
            #pragma unroll
            for (int jj = 0; jj < 4; jj++) acc[ii][jj] = 0.f;
        #pragma unroll 8
        for (int d = 0; d < DKK; d++) {
            float qa[4], kv[4];
            #pragma unroll
            for (int ii = 0; ii < 4; ii++) qa[ii] = sq[(ti * 4 + ii) * 25 + d];
            #pragma unroll
            for (int jj = 0; jj < 4; jj++) kv[jj] = sk[(tj + 16 * jj) * 25 + d];
            #pragma unroll
            for (int ii = 0; ii < 4; ii++)
                #pragma unroll
                for (int jj = 0; jj < 4; jj++) acc[ii][jj] += qa[ii] * kv[jj];
        }
        #pragma unroll
        for (int ii = 0; ii < 4; ii++) {
            int i = ti * 4 + ii;
            #pragma unroll
            for (int jj = 0; jj < 4; jj++) {
                int j = tj + 16 * jj;
                sa[i * 65 + j] = (sa[i * 65 + j] + acc[ii][jj]) * scale + smb[j];
            }
        }
    }
    for (int idx = tid; idx < NN * TEE; idx += 256) qbe[idx] = 0.f;
    for (int idx = tid; idx < NN * TDD; idx += 256) qbd[idx] = 0.f;
    for (int idx = tid; idx < TEE * DKK; idx += 256) {
        int t = idx / DKK, d = idx % DKK;
        ve[t * 25 + d] = ev_t[(long)(t * HH + h) * DKK + d];
    }
    for (int idx = tid; idx < TDD * DKK; idx += 256) {
        int t = idx / DKK, d = idx % DKK;
        vd[t * 25 + d] = dv_t[(long)(t * HH + h) * DKK + d];
    }
    __syncthreads();

    // ---- phase 5: softmax + toeplitz + type scatter (bins from registers) --
    #pragma unroll
    for (int r = 0; r < 8; r++) {
        int i = warp + 8 * r;
        int c0v = cd[r] & 0xff, d0v = (cd[r] >> 8) & 0xff;
        int c1v = (cd[r] >> 16) & 0xff, d1v = cd[r] >> 24;
        float v0 = sa[i * 65 + lane];
        float v1 = sa[i * 65 + 32 + lane];
        float m = fmaxf(v0, v1);
        #pragma unroll
        for (int o = 16; o > 0; o >>= 1) m = fmaxf(m, __shfl_xor_sync(0xffffffffu, m, o));
        float e0 = __expf(v0 - m);
        float e1 = __expf(v1 - m);
        float s = e0 + e1;
        #pragma unroll
        for (int o = 16; o > 0; o >>= 1) s += __shfl_xor_sync(0xffffffffu, s, o);
        float inv = __frcp_rn(s);
        {
            int j = lane;
            float t = (j >= i) ? str[j - i] : stc[i - j];
            float av = e0 * inv * t;
            sa[i * 65 + j] = av;
            atomicAdd(&qbe[i * 32 + c0v], av);
            atomicAdd(&qbd[i * 40 + d0v], av);
        }
        {
            int j = lane + 32;
            float t = (j >= i) ? str[j - i] : stc[i - j];
            float av = e1 * inv * t;
            sa[i * 65 + j] = av;
            atomicAdd(&qbe[i * 32 + c1v], av);
            atomicAdd(&qbd[i * 40 + d1v], av);
        }
    }
    __syncthreads();

    // ---- phase 6: z = a@v + s_e@Ve + s_d@Vd -> split bf16 output -----------
    if (tid < 128) {
        const int ip = tid >> 2, dg = tid & 3;
        const int i0 = ip * 2, d0 = dg * 6;
        float acc[2][6];
        #pragma unroll
        for (int a = 0; a < 2; a++)
            #pragma unroll
            for (int x = 0; x < 6; x++) acc[a][x] = 0.f;
        #pragma unroll 4
        for (int j = 0; j < NN; j++) {
            float a0 = sa[i0 * 65 + j], a1 = sa[(i0 + 1) * 65 + j];
            #pragma unroll
            for (int x = 0; x < 6; x++) {
                float v = sv[j * 25 + d0 + x];
                acc[0][x] += a0 * v;
                acc[1][x] += a1 * v;
            }
        }
        #pragma unroll 4
        for (int t = 0; t < TEE; t++) {
            float a0 = qbe[i0 * 32 + t], a1 = qbe[(i0 + 1) * 32 + t];
            #pragma unroll
            for (int x = 0; x < 6; x++) {
                float v = ve[t * 25 + d0 + x];
                acc[0][x] += a0 * v;
                acc[1][x] += a1 * v;
            }
        }
        #pragma unroll 4
        for (int t = 0; t < TDD; t++) {
            float a0 = qbd[i0 * 40 + t], a1 = qbd[(i0 + 1) * 40 + t];
            #pragma unroll
            for (int x = 0; x < 6; x++) {
                float v = vd[t * 25 + d0 + x];
                acc[0][x] += a0 * v;
                acc[1][x] += a1 * v;
            }
        }
        #pragma unroll
        for (int a = 0; a < 2; a++) {
            long off = (long)(b * NN + i0 + a) * DD + h * DKK + d0;
            #pragma unroll
            for (int x = 0; x < 6; x++) {
                float v = acc[a][x];
                __nv_bfloat16 hi = __float2bfloat16(v);
                __nv_bfloat16 lo = __float2bfloat16(v - __bfloat162float(hi));
                zh[off + x] = hi;
                zl[off + x] = lo;
            }
        }
    }
}

// ---------------- host launch ------------------------------------------------
extern "C" void kernel_launch(void* const* d_in, const int* in_sizes, int n_in,
                              void* d_out, int out_size)
{
    const float* node  = (const float*)d_in[0];
    const int*   dist  = (const int*)d_in[1];
    const int*   conn  = (const int*)d_in[2];
    const int*   traj  = (const int*)d_in[3];
    const unsigned char* mask = (const unsigned char*)d_in[4];
    const float* W_qkv = (const float*)d_in[5];
    const float* b_qkv = (const float*)d_in[6];
    const float* W_out = (const float*)d_in[7];
    const float* b_out = (const float*)d_in[8];
    const float* eq_t  = (const float*)d_in[9];
    const float* ek_t  = (const float*)d_in[10];
    const float* dq_t  = (const float*)d_in[11];
    const float* dk_t  = (const float*)d_in[12];
    const float* pemb  = (const float*)d_in[13];
    const float* ppw   = (const float*)d_in[14];
    const float* ev_t  = (const float*)d_in[15];
    const float* dv_t  = (const float*)d_in[16];
    const float* tr    = (const float*)d_in[17];
    const float* tc    = (const float*)d_in[18];
    float* out = (float*)d_out;

    float *qkv_s, *pb_s;
    __nv_bfloat16 *Ah, *Al, *Bh, *Bl;
    cudaGetSymbolAddress((void**)&qkv_s, g_qkv);
    cudaGetSymbolAddress((void**)&pb_s,  g_pb);
    cudaGetSymbolAddress((void**)&Ah, g_Ah);
    cudaGetSymbolAddress((void**)&Al, g_Al);
    cudaGetSymbolAddress((void**)&Bh, g_Bh);
    cudaGetSymbolAddress((void**)&Bl, g_Bl);

    cudaFuncSetAttribute(mma_gemm_kernel, cudaFuncAttributeMaxDynamicSharedMemorySize, GM_SMEM);
    cudaFuncSetAttribute(attn_kernel, cudaFuncAttributeMaxDynamicSharedMemorySize, SMEM_BYTES);

    const int nA = BB * NN * DD;   // 8192*768

    // path-bias precompute
    pb_kernel<<<(BB * NN * NN) / 128, 256>>>(traj, dist, pemb, ppw, pb_s);

    // QKV projection via mma.sync bf16x3
    ksplit<<<nA / 4 / 256, 256>>>(node, Ah, Al, nA);
    ksplitT<<<dim3(NQKV / 32, DD / 32), dim3(32, 8)>>>(W_qkv, Bh, Bl, DD, NQKV);
    mma_gemm_kernel<<<dim3(NQKV / 128, (BB * NN) / 128), 256, GM_SMEM>>>(
        Ah, Al, Bh, Bl, b_qkv, qkv_s, NQKV);

    // fused attention -> writes z directly as split bf16 into Ah/Al
    attn_kernel<<<dim3(HH, BB), 256, SMEM_BYTES>>>(
        qkv_s, dist, conn, pb_s, mask,
        eq_t, ek_t, dq_t, dk_t, ev_t, dv_t, tr, tc, Ah, Al);

    // output projection via mma.sync bf16x3 (no ksplit pass needed)
    ksplitT<<<dim3(DD / 32, DD / 32), dim3(32, 8)>>>(W_out, Bh, Bl, DD, DD);
    mma_gemm_kernel<<<dim3(DD / 128, (BB * NN) / 128), 256, GM_SMEM>>>(
        Ah, Al, Bh, Bl, b_out, out, DD);
}

// round 15
// speedup vs baseline: 1.6474x; 1.6474x over previous
#include <cuda_runtime.h>
#include <cuda_bf16.h>
#include <math.h>
#include <stdint.h>

// Problem constants
#define BB 128
#define NN 64
#define DD 768
#define HH 32
#define DKK 24
#define LL 4
#define TEE 32
#define TDD 40
#define VPP 512
#define NQKV 2304   // 3*H*DK

// ---------------- scratch (device globals; no dynamic alloc) ----------------
__device__ float g_qkv[BB * NN * NQKV];            // [8192, 2304] f32
__device__ float g_pb [BB * HH * NN * NN];         // path bias [b,h,i,j]
__device__ __nv_bfloat16 g_Ah[BB * NN * DD];       // A hi  [8192,768]
__device__ __nv_bfloat16 g_Al[BB * NN * DD];       // A lo
__device__ __nv_bfloat16 g_Bh[NQKV * DD];          // B hi  [N,K]
__device__ __nv_bfloat16 g_Bl[NQKV * DD];          // B lo

// ======================= PTX helpers (base-target safe) =====================
__device__ __forceinline__ uint32_t smem_u32(const void* p) {
    uint32_t a;
    asm("{ .reg .u64 t; cvta.to.shared.u64 t, %1; cvt.u32.u64 %0, t; }" : "=r"(a) : "l"(p));
    return a;
}

#define CPASYNC16(dst, src) \
    asm volatile("cp.async.cg.shared.global [%0], [%1], 16;" :: "r"(dst), "l"(src) : "memory")
#define CPCOMMIT() asm volatile("cp.async.commit_group;" ::: "memory")
#define CPWAIT1()  asm volatile("cp.async.wait_group 1;" ::: "memory")

#define LDMX4(r0, r1, r2, r3, addr) \
    asm volatile("ldmatrix.sync.aligned.m8n8.x4.shared.b16 {%0,%1,%2,%3}, [%4];" \
        : "=r"(r0), "=r"(r1), "=r"(r2), "=r"(r3) : "r"(addr))

#define MMA16816(d, a, b0, b1) \
    asm volatile("mma.sync.aligned.m16n8k16.row.col.f32.bf16.bf16.f32 " \
        "{%0,%1,%2,%3}, {%4,%5,%6,%7}, {%8,%9}, {%0,%1,%2,%3};" \
        : "+f"((d)[0]), "+f"((d)[1]), "+f"((d)[2]), "+f"((d)[3]) \
        : "r"((a)[0]), "r"((a)[1]), "r"((a)[2]), "r"((a)[3]), "r"(b0), "r"(b1))

// ======================= prep kernels =======================================
__global__ void __launch_bounds__(256) ksplit(const float* __restrict__ X,
                                              __nv_bfloat16* __restrict__ H,
                                              __nv_bfloat16* __restrict__ L, int n)
{
    int i = (blockIdx.x * 256 + threadIdx.x) * 4;
    if (i >= n) return;
    float4 v = *(const float4*)(X + i);
    __nv_bfloat16 h0 = __float2bfloat16(v.x), h1 = __float2bfloat16(v.y);
    __nv_bfloat16 h2 = __float2bfloat16(v.z), h3 = __float2bfloat16(v.w);
    __nv_bfloat16 l0 = __float2bfloat16(v.x - __bfloat162float(h0));
    __nv_bfloat16 l1 = __float2bfloat16(v.y - __bfloat162float(h1));
    __nv_bfloat16 l2 = __float2bfloat16(v.z - __bfloat162float(h2));
    __nv_bfloat16 l3 = __float2bfloat16(v.w - __bfloat162float(h3));
    ((__nv_bfloat162*)(H + i))[0] = __nv_bfloat162(h0, h1);
    ((__nv_bfloat162*)(H + i))[1] = __nv_bfloat162(h2, h3);
    ((__nv_bfloat162*)(L + i))[0] = __nv_bfloat162(l0, l1);
    ((__nv_bfloat162*)(L + i))[1] = __nv_bfloat162(l2, l3);
}

// W[K,N] f32 -> H,L [N,K] bf16 (transpose + split)
__global__ void __launch_bounds__(256) ksplitT(const float* __restrict__ W,
                                               __nv_bfloat16* __restrict__ H,
                                               __nv_bfloat16* __restrict__ L,
                                               int K, int N)
{
    __shared__ float t[32][33];
    int n0 = blockIdx.x * 32, k0 = blockIdx.y * 32;
    int tx = threadIdx.x, ty = threadIdx.y;
    #pragma unroll
    for (int r = ty; r < 32; r += 8)
        t[r][tx] = W[(long)(k0 + r) * N + n0 + tx];
    __syncthreads();
    #pragma unroll
    for (int r = ty; r < 32; r += 8) {
        float v = t[tx][r];
        __nv_bfloat16 h = __float2bfloat16(v);
        __nv_bfloat16 l = __float2bfloat16(v - __bfloat162float(h));
        long o = (long)(n0 + r) * K + k0 + tx;
        H[o] = h;
        L[o] = l;
    }
}

// ======================= path-bias precompute ===============================
__global__ void __launch_bounds__(256) pb_kernel(
    const int* __restrict__ traj, const int* __restrict__ distance,
    const float* __restrict__ path_emb, const float* __restrict__ path_pos,
    float* __restrict__ pb_out)
{
    __shared__ __align__(16) int stg[8][200];
    __shared__ __align__(16) float tile[32][132];
    const int tid = threadIdx.x, w = tid >> 5, lane = tid & 31;
    const long e0 = (long)blockIdx.x * 128;
    const int we0 = w * 16;

    float wl[4];
    #pragma unroll
    for (int l = 0; l < 4; l++) wl[l] = path_pos[l * HH + lane];

    const int4* src = (const int4*)(traj + (e0 + we0) * 12);
    ((int4*)stg[w])[lane] = src[lane];
    if (lane < 16) ((int4*)stg[w])[32 + lane] = src[32 + lane];
    int ddv = 0;
    if (lane < 16) ddv = distance[e0 + we0 + lane];
    __syncwarp();

    #pragma unroll 4
    for (int k = 0; k < 16; k++) {
        int dd = __shfl_sync(0xffffffffu, ddv, k);
        const int* tj = &stg[w][k * 12];
        float acc = 0.f;
        #pragma unroll
        for (int l = 0; l < 4; l++) {
            float s3 = path_emb[tj[3 * l + 0] * HH + lane]
                     + path_emb[tj[3 * l + 1] * HH + lane]
                     + path_emb[tj[3 * l + 2] * HH + lane];
            acc += wl[l] * s3;
        }
        tile[lane][we0 + k] = acc * __frcp_rn(fmaxf((float)dd, 1.f));
    }
    __syncthreads();

    const int row = tid >> 3;
    const int c0 = (tid & 7) * 16;
    const long b = e0 >> 12;
    const long ijo = e0 & 4095;
    float* orow = pb_out + ((b * HH + row) << 12) + ijo;
    #pragma unroll
    for (int k2 = 0; k2 < 4; k2++) {
        float4 v = *(float4*)&tile[row][c0 + k2 * 4];
        *(float4*)&orow[c0 + k2 * 4] = v;
    }
}

// ======================= mma.sync GEMM (bf16x3) =============================
// 128x128x32 tile, 8 warps, 3-stage cp.async pipeline, 1 barrier/iter.
// SMEM rows: 64B (32 bf16), XOR chunk swizzle chunk'=(chunk+(row>>1))&3.
// R10-proven ordering: prefetch BEFORE LDSM (keeps regs at 128, 2 CTAs/SM).
#define GTILEB 8192                    // 128 rows * 64B
#define GM_STAGEB (4 * GTILEB)         // 32768 (Ah,Al,Bh,Bl)
#define GM_SMEM (3 * GM_STAGEB)        // 98304

__device__ __forceinline__ int swofs(int r, int ch) {
    return r * 64 + (((ch + (r >> 1)) & 3) << 4);
}

__global__ void __launch_bounds__(256, 2) mma_gemm_kernel(
    const __nv_bfloat16* __restrict__ Ah, const __nv_bfloat16* __restrict__ Al,
    const __nv_bfloat16* __restrict__ Bh, const __nv_bfloat16* __restrict__ Bl,
    const float* __restrict__ bias, float* __restrict__ C, int Ncols)
{
    extern __shared__ char smem[];
    const uint32_t sb = smem_u32(smem);
    const int tid = threadIdx.x, wid = tid >> 5, lane = tid & 31;
    const int nT = blockIdx.x, mT = blockIdx.y;
    const int wm = wid >> 1;
    const int wn = wid & 1;

    const __nv_bfloat16* srcA_h = Ah + (long)(mT * 128) * DD;
    const __nv_bfloat16* srcA_l = Al + (long)(mT * 128) * DD;
    const __nv_bfloat16* srcB_h = Bh + (long)(nT * 128) * DD;
    const __nv_bfloat16* srcB_l = Bl + (long)(nT * 128) * DD;

    float acc[2][8][4];
    #pragma unroll
    for (int s = 0; s < 2; s++)
        #pragma unroll
        for (int f = 0; f < 8; f++)
            #pragma unroll
            for (int x = 0; x < 4; x++) acc[s][f][x] = 0.f;

    auto load_stage = [&](int st, int k0) {
        uint32_t sbase = sb + st * GM_STAGEB;
        #pragma unroll
        for (int i = 0; i < 8; i++) {
            int idx = ((i & 1) << 8) + tid;
            int row = idx >> 2, ch = idx & 3;
            const __nv_bfloat16* src;
            switch (i >> 1) {
                case 0: src = srcA_h; break;
                case 1: src = srcA_l; break;
                case 2: src = srcB_h; break;
                default: src = srcB_l; break;
            }
            src += (long)row * DD + k0 + ch * 8;
            uint32_t dst = sbase + (i >> 1) * GTILEB + swofs(row, ch);
            CPASYNC16(dst, src);
        }
        CPCOMMIT();
    };

    load_stage(0, 0);
    load_stage(1, 32);

    const int arow = wm * 32 + (lane & 15);
    const int chq = lane >> 4;                     // 0 or 1

    for (int c = 0; c < 24; c++) {
        CPWAIT1();
        __syncthreads();
        if (c + 2 < 24) load_stage((c + 2) % 3, (c + 2) * 32);
        else CPCOMMIT();                            // keep wait depth uniform

        uint32_t st = sb + (c % 3) * GM_STAGEB;
        uint32_t sAh = st, sAl = st + GTILEB, sBh = st + 2 * GTILEB, sBl = st + 3 * GTILEB;

        #pragma unroll
        for (int kk = 0; kk < 2; kk++) {
            const int ch = kk * 2 + chq;
            uint32_t ah[2][4], al[2][4], bh[4][4], bl[4][4];
            LDMX4(ah[0][0], ah[0][1], ah[0][2], ah[0][3], sAh + swofs(arow, ch));
            LDMX4(ah[1][0], ah[1][1], ah[1][2], ah[1][3], sAh + swofs(arow + 16, ch));
            LDMX4(al[0][0], al[0][1], al[0][2], al[0][3], sAl + swofs(arow, ch));
            LDMX4(al[1][0], al[1][1], al[1][2], al[1][3], sAl + swofs(arow + 16, ch));
            #pragma unroll
            for (int g = 0; g < 4; g++) {
                int brow = wn * 64 + g * 16 + (lane & 15);
                LDMX4(bh[g][0], bh[g][1], bh[g][2], bh[g][3], sBh + swofs(brow, ch));
                LDMX4(bl[g][0], bl[g][1], bl[g][2], bl[g][3], sBl + swofs(brow, ch));
            }
            #pragma unroll
            for (int s = 0; s < 2; s++)
                #pragma unroll
                for (int f = 0; f < 8; f++) {
                    int g = f >> 1, p = f & 1;
                    MMA16816(acc[s][f], ah[s], bh[g][p], bh[g][p + 2]);
                    MMA16816(acc[s][f], ah[s], bl[g][p], bl[g][p + 2]);
                    MMA16816(acc[s][f], al[s], bh[g][p], bh[g][p + 2]);
                }
        }
    }

    #pragma unroll
    for (int s = 0; s < 2; s++) {
        int r0 = mT * 128 + wm * 32 + s * 16 + (lane >> 2);
        #pragma unroll
        for (int f = 0; f < 8; f++) {
            int col = nT * 128 + wn * 64 + f * 8 + (lane & 3) * 2;
            float b0 = bias[col], b1 = bias[col + 1];
            float2 v0 = make_float2(acc[s][f][0] + b0, acc[s][f][1] + b1);
            float2 v1 = make_float2(acc[s][f][2] + b0, acc[s][f][3] + b1);
            *(float2*)&C[(long)r0 * Ncols + col] = v0;
            *(float2*)&C[(long)(r0 + 8) * Ncols + col] = v1;
        }
    }
}

// ---------------- fused attention: one CTA per (b,h) ------------------------
#define OFF_SQ   0
#define OFF_SK   1600
#define OFF_SV   3200
#define OFF_QBE  4800
#define OFF_QBD  6848
#define OFF_KBE  9408
#define OFF_KBD  11456
#define OFF_VE   9408
#define OFF_VD   11456
#define OFF_SA   14016
#define OFF_EQE  14016
#define OFF_EKE  14816
#define OFF_EQD  15616
#define OFF_EKD  16616
#define OFF_STR  18176
#define OFF_STC  18240
#define OFF_SMB  18304
#define SMEM_FLOATS 18368
#define SMEM_BYTES  (SMEM_FLOATS * 4)   /* 73472 -> 3 CTAs/SM */

__global__ void __launch_bounds__(256, 3) attn_kernel(
    const float* __restrict__ qkv,
    const int* __restrict__ distance,
    const int* __restrict__ conn,
    const float* __restrict__ pb,
    const unsigned char* __restrict__ mask,
    const float* __restrict__ eq_t, const float* __restrict__ ek_t,
    const float* __restrict__ dq_t, const float* __restrict__ dk_t,
    const float* __restrict__ ev_t, const float* __restrict__ dv_t,
    const float* __restrict__ toep_r, const float* __restrict__ toep_c,
    __nv_bfloat16* __restrict__ zh, __nv_bfloat16* __restrict__ zl)
{
    extern __shared__ float sm[];
    float* sq  = sm + OFF_SQ;
    float* sk  = sm + OFF_SK;
    float* sv  = sm + OFF_SV;
    float* qbe = sm + OFF_QBE;
    float* qbd = sm + OFF_QBD;
    float* kbe = sm + OFF_KBE;
    float* kbd = sm + OFF_KBD;
    float* ve  = sm + OFF_VE;
    float* vd  = sm + OFF_VD;
    float* sa  = sm + OFF_SA;
    float* eqe = sm + OFF_EQE;
    float* eke = sm + OFF_EKE;
    float* eqd = sm + OFF_EQD;
    float* ekd = sm + OFF_EKD;
    float* str = sm + OFF_STR;
    float* stc = sm + OFF_STC;
    float* smb = sm + OFF_SMB;

    const int h = blockIdx.x;
    const int b = blockIdx.y;
    const int tid = threadIdx.x;
    const int warp = tid >> 5, lane = tid & 31;

    // ---- phase 1: loads ----
    for (int idx = tid; idx < NN * DKK; idx += 256) {
        int i = idx / DKK, d = idx % DKK;
        long base = (long)(b * NN + i) * NQKV + h * DKK + d;
        sq[i * 25 + d] = qkv[base];
        sk[i * 25 + d] = qkv[base + HH * DKK];
        sv[i * 25 + d] = qkv[base + 2 * HH * DKK];
    }
    for (int idx = tid; idx < TEE * DKK; idx += 256) {
        int t = idx / DKK, d = idx % DKK;
        long g = (long)(t * HH + h) * DKK + d;
        eqe[t * 25 + d] = eq_t[g];
        eke[t * 25 + d] = ek_t[g];
    }
    for (int idx = tid; idx < TDD * DKK; idx += 256) {
        int t = idx / DKK, d = idx % DKK;
        long g = (long)(t * HH + h) * DKK + d;
        eqd[t * 25 + d] = dq_t[g];
        ekd[t * 25 + d] = dk_t[g];
    }
    if (tid < NN) {
        str[tid] = toep_r[h * NN + tid];
        stc[tid] = toep_c[h * NN + tid];
        smb[tid] = mask[b * NN + tid] ? -1e30f : 0.f;
    }
    __syncthreads();

    // ---- phase 2a: qb tables (64x72 fused) ----
    {
        const int ip = tid >> 3, tg = tid & 7;
        const int i0 = ip * 2;
        float a0[9], a1[9];
        const float* tp[9];
        #pragma unroll
        for (int k = 0; k < 9; k++) {
            int t = tg * 9 + k;
            tp[k] = (t < TEE) ? (eke + t * 25) : (ekd + (t - TEE) * 25);
            a0[k] = 0.f; a1[k] = 0.f;
        }
        #pragma unroll 8
        for (int d = 0; d < DKK; d++) {
            float q0 = sq[i0 * 25 + d], q1 = sq[(i0 + 1) * 25 + d];
            #pragma unroll
            for (int k = 0; k < 9; k++) {
                float e = tp[k][d];
                a0[k] += q0 * e;
                a1[k] += q1 * e;
            }
        }
        #pragma unroll
        for (int k = 0; k < 9; k++) {
            int t = tg * 9 + k;
            if (t < TEE) {
                qbe[i0 * 32 + t] = a0[k];
                qbe[(i0 + 1) * 32 + t] = a1[k];
            } else {
                qbd[i0 * 40 + t - TEE] = a0[k];
                qbd[(i0 + 1) * 40 + t - TEE] = a1[k];
            }
        }
    }
    // ---- phase 2b: kb tables (72x64 fused) ----
    if (tid < 192) {
        const int tt = tid >> 3, jg = tid & 7;
        float ac[3][8];
        const float* ep[3];
        #pragma unroll
        for (int c = 0; c < 3; c++) {
            int t = tt * 3 + c;
            ep[c] = (t < TEE) ? (eqe + t * 25) : (eqd + (t - TEE) * 25);
            #pragma unroll
            for (int jj = 0; jj < 8; jj++) ac[c][jj] = 0.f;
        }
        #pragma unroll 8
        for (int d = 0; d < DKK; d++) {
            float e0 = ep[0][d], e1 = ep[1][d], e2 = ep[2][d];
            #pragma unroll
            for (int jj = 0; jj < 8; jj++) {
                float kv = sk[(jg + 8 * jj) * 25 + d];
                ac[0][jj] += e0 * kv;
                ac[1][jj] += e1 * kv;
                ac[2][jj] += e2 * kv;
            }
        }
        #pragma unroll
        for (int c = 0; c < 3; c++) {
            int t = tt * 3 + c;
            #pragma unroll
            for (int jj = 0; jj < 8; jj++) {
                int j = jg + 8 * jj;
                if (t < TEE) kbe[t * 64 + j] = ac[c][jj];
                else         kbd[(t - TEE) * 64 + j] = ac[c][jj];
            }
        }
    }
    __syncthreads();

    // ---- phase 3: gathers + path bias -> sa, (warp,lane) layout ------------
    const long base_bij = (long)b * (NN * NN);
    const float* pbh = pb + (((long)(b * HH + h)) << 12);
    unsigned int cd[8];
    #pragma unroll
    for (int r = 0; r < 8; r++) {
        int i = warp + 8 * r;
        int c0 = conn[base_bij + i * 64 + lane];
        int d0 = distance[base_bij + i * 64 + lane];
        int c1 = conn[base_bij + i * 64 + 32 + lane];
        int d1 = distance[base_bij + i * 64 + 32 + lane];
        cd[r] = (unsigned)c0 | ((unsigned)d0 << 8) | ((unsigned)c1 << 16) | ((unsigned)d1 << 24);
        sa[i * 65 + lane] = qbe[i * 32 + c0] + kbe[c0 * 64 + lane]
                          + qbd[i * 40 + d0] + kbd[d0 * 64 + lane]
                          + pbh[i * 64 + lane];
        sa[i * 65 + 32 + lane] = qbe[i * 32 + c1] + kbe[c1 * 64 + 32 + lane]
                               + qbd[i * 40 + d1] + kbd[d1 * 64 + 32 + lane]
                               + pbh[i * 64 + 32 + lane];
    }
    __syncthreads();

    // ---- phase 4: QK dot (4i x 4j tile); zero accumulators; load Ve/Vd -----
    const float scale = 0.2041241452319315f;
    {
        const int ti = tid >> 4, tj = tid & 15;
        float acc[4][4];
        #pragma unroll
        for (int ii = 0; ii < 4; ii++)
            #pragma unroll
            for (int jj = 0; jj < 4; jj++) acc[ii][jj] = 0.f;
        #pragma unroll 8
        for (int d = 0; d < DKK; d++) {
            float qa[4], kv[4];
            #pragma unroll
            for (int ii = 0; ii < 4; ii++) qa[ii] = sq[(ti * 4 + ii) * 25 + d];
            #pragma unroll
            for (int jj = 0; jj < 4; jj++) kv[jj] = sk[(tj + 16 * jj) * 25 + d];
            #pragma unroll
            for (int ii = 0; ii < 4; ii++)
                #pragma unroll
                for (int jj = 0; jj < 4; jj++) acc[ii][jj] += qa[ii] * kv[jj];
        }
        #pragma unroll
        for (int ii = 0; ii < 4; ii++) {
            int i = ti * 4 + ii;
            #pragma unroll
            for (int jj = 0; jj < 4; jj++) {
                int j = tj + 16 * jj;
                sa[i * 65 + j] = (sa[i * 65 + j] + acc[ii][jj]) * scale + smb[j];
            }
        }
    }
    for (int idx = tid; idx < NN * TEE; idx += 256) qbe[idx] = 0.f;
    for (int idx = tid; idx < NN * TDD; idx += 256) qbd[idx] = 0.f;
    for (int idx = tid; idx < TEE * DKK; idx += 256) {
        int t = idx / DKK, d = idx % DKK;
        ve[t * 25 + d] = ev_t[(long)(t * HH + h) * DKK + d];
    }
    for (int idx = tid; idx < TDD * DKK; idx += 256) {
        int t = idx / DKK, d = idx % DKK;
        vd[t * 25 + d] = dv_t[(long)(t * HH + h) * DKK + d];
    }
    __syncthreads();

    // ---- phase 5: softmax + toeplitz + type scatter (bins from registers) --
    #pragma unroll
    for (int r = 0; r < 8; r++) {
        int i = warp + 8 * r;
        int c0v = cd[r] & 0xff, d0v = (cd[r] >> 8) & 0xff;
        int c1v = (cd[r] >> 16) & 0xff, d1v = cd[r] >> 24;
        float v0 = sa[i * 65 + lane];
        float v1 = sa[i * 65 + 32 + lane];
        float m = fmaxf(v0, v1);
        #pragma unroll
        for (int o = 16; o > 0; o >>= 1) m = fmaxf(m, __shfl_xor_sync(0xffffffffu, m, o));
        float e0 = __expf(v0 - m);
        float e1 = __expf(v1 - m);
        float s = e0 + e1;
        #pragma unroll
        for (int o = 16; o > 0; o >>= 1) s += __shfl_xor_sync(0xffffffffu, s, o);
        float inv = __frcp_rn(s);
        {
            int j = lane;
            float t = (j >= i) ? str[j - i] : stc[i - j];
            float av = e0 * inv * t;
            sa[i * 65 + j] = av;
            atomicAdd(&qbe[i * 32 + c0v], av);
            atomicAdd(&qbd[i * 40 + d0v], av);
        }
        {
            int j = lane + 32;
            float t = (j >= i) ? str[j - i] : stc[i - j];
            float av = e1 * inv * t;
            sa[i * 65 + j] = av;
            atomicAdd(&qbe[i * 32 + c1v], av);
            atomicAdd(&qbd[i * 40 + d1v], av);
        }
    }
    __syncthreads();

    // ---- phase 6: z = a@v + s_e@Ve + s_d@Vd -> split bf16 output -----------
    if (tid < 128) {
        const int ip = tid >> 2, dg = tid & 3;
        const int i0 = ip * 2, d0 = dg * 6;
        float acc[2][6];
        #pragma unroll
        for (int a = 0; a < 2; a++)
            #pragma unroll
            for (int x = 0; x < 6; x++) acc[a][x] = 0.f;
        #pragma unroll 4
        for (int j = 0; j < NN; j++) {
            float a0 = sa[i0 * 65 + j], a1 = sa[(i0 + 1) * 65 + j];
            #pragma unroll
            for (int x = 0; x < 6; x++) {
                float v = sv[j * 25 + d0 + x];
                acc[0][x] += a0 * v;
                acc[1][x] += a1 * v;
            }
        }
        #pragma unroll 4
        for (int t = 0; t < TEE; t++) {
            float a0 = qbe[i0 * 32 + t], a1 = qbe[(i0 + 1) * 32 + t];
            #pragma unroll
            for (int x = 0; x < 6; x++) {
                float v = ve[t * 25 + d0 + x];
                acc[0][x] += a0 * v;
                acc[1][x] += a1 * v;
            }
        }
        #pragma unroll 4
        for (int t = 0; t < TDD; t++) {
            float a0 = qbd[i0 * 40 + t], a1 = qbd[(i0 + 1) * 40 + t];
            #pragma unroll
            for (int x = 0; x < 6; x++) {
                float v = vd[t * 25 + d0 + x];
                acc[0][x] += a0 * v;
                acc[1][x] += a1 * v;
            }
        }
        #pragma unroll
        for (int a = 0; a < 2; a++) {
            long off = (long)(b * NN + i0 + a) * DD + h * DKK + d0;
            #pragma unroll
            for (int x = 0; x < 6; x++) {
                float v = acc[a][x];
                __nv_bfloat16 hi = __float2bfloat16(v);
                __nv_bfloat16 lo = __float2bfloat16(v - __bfloat162float(hi));
                zh[off + x] = hi;
                zl[off + x] = lo;
            }
        }
    }
}

// ---------------- host launch ------------------------------------------------
extern "C" void kernel_launch(void* const* d_in, const int* in_sizes, int n_in,
                              void* d_out, int out_size)
{
    const float* node  = (const float*)d_in[0];
    const int*   dist  = (const int*)d_in[1];
    const int*   conn  = (const int*)d_in[2];
    const int*   traj  = (const int*)d_in[3];
    const unsigned char* mask = (const unsigned char*)d_in[4];
    const float* W_qkv = (const float*)d_in[5];
    const float* b_qkv = (const float*)d_in[6];
    const float* W_out = (const float*)d_in[7];
    const float* b_out = (const float*)d_in[8];
    const float* eq_t  = (const float*)d_in[9];
    const float* ek_t  = (const float*)d_in[10];
    const float* dq_t  = (const float*)d_in[11];
    const float* dk_t  = (const float*)d_in[12];
    const float* pemb  = (const float*)d_in[13];
    const float* ppw   = (const float*)d_in[14];
    const float* ev_t  = (const float*)d_in[15];
    const float* dv_t  = (const float*)d_in[16];
    const float* tr    = (const float*)d_in[17];
    const float* tc    = (const float*)d_in[18];
    float* out = (float*)d_out;

    float *qkv_s, *pb_s;
    __nv_bfloat16 *Ah, *Al, *Bh, *Bl;
    cudaGetSymbolAddress((void**)&qkv_s, g_qkv);
    cudaGetSymbolAddress((void**)&pb_s,  g_pb);
    cudaGetSymbolAddress((void**)&Ah, g_Ah);
    cudaGetSymbolAddress((void**)&Al, g_Al);
    cudaGetSymbolAddress((void**)&Bh, g_Bh);
    cudaGetSymbolAddress((void**)&Bl, g_Bl);

    cudaFuncSetAttribute(mma_gemm_kernel, cudaFuncAttributeMaxDynamicSharedMemorySize, GM_SMEM);
    cudaFuncSetAttribute(attn_kernel, cudaFuncAttributeMaxDynamicSharedMemorySize, SMEM_BYTES);

    const int nA = BB * NN * DD;   // 8192*768

    // path-bias precompute
    pb_kernel<<<(BB * NN * NN) / 128, 256>>>(traj, dist, pemb, ppw, pb_s);

    // QKV projection via mma.sync bf16x3
    ksplit<<<nA / 4 / 256, 256>>>(node, Ah, Al, nA);
    ksplitT<<<dim3(NQKV / 32, DD / 32), dim3(32, 8)>>>(W_qkv, Bh, Bl, DD, NQKV);
    mma_gemm_kernel<<<dim3(NQKV / 128, (BB * NN) / 128), 256, GM_SMEM>>>(
        Ah, Al, Bh, Bl, b_qkv, qkv_s, NQKV);

    // fused attention -> writes z directly as split bf16 into Ah/Al
    attn_kernel<<<dim3(HH, BB), 256, SMEM_BYTES>>>(
        qkv_s, dist, conn, pb_s, mask,
        eq_t, ek_t, dq_t, dk_t, ev_t, dv_t, tr, tc, Ah, Al);

    // output projection via mma.sync bf16x3 (no ksplit pass needed)
    ksplitT<<<dim3(DD / 32, DD / 32), dim3(32, 8)>>>(W_out, Bh, Bl, DD, DD);
    mma_gemm_kernel<<<dim3(DD / 128, (BB * NN) / 128), 256, GM_SMEM>>>(
        Ah, Al, Bh, Bl, b_out, out, DD);
}

// round 16
// speedup vs baseline: 1.6635x; 1.0097x over previous
#include <cuda_runtime.h>
#include <cuda_bf16.h>
#include <math.h>
#include <stdint.h>

// Problem constants
#define BB 128
#define NN 64
#define DD 768
#define HH 32
#define DKK 24
#define LL 4
#define TEE 32
#define TDD 40
#define VPP 512
#define NQKV 2304   // 3*H*DK

// ---------------- scratch (device globals; no dynamic alloc) ----------------
__device__ float g_qkv[BB * NN * NQKV];            // [8192, 2304] f32
__device__ float g_pb [BB * HH * NN * NN];         // path bias [b,h,i,j]
__device__ __nv_bfloat16 g_Ah[BB * NN * DD];       // A hi  [8192,768]
__device__ __nv_bfloat16 g_Al[BB * NN * DD];       // A lo
__device__ __nv_bfloat16 g_Bh[NQKV * DD];          // B hi  [N,K]
__device__ __nv_bfloat16 g_Bl[NQKV * DD];          // B lo

// ======================= PTX helpers (base-target safe) =====================
__device__ __forceinline__ uint32_t smem_u32(const void* p) {
    uint32_t a;
    asm("{ .reg .u64 t; cvta.to.shared.u64 t, %1; cvt.u32.u64 %0, t; }" : "=r"(a) : "l"(p));
    return a;
}

#define CPASYNC16(dst, src) \
    asm volatile("cp.async.cg.shared.global [%0], [%1], 16;" :: "r"(dst), "l"(src) : "memory")
#define CPCOMMIT() asm volatile("cp.async.commit_group;" ::: "memory")
#define CPWAIT1()  asm volatile("cp.async.wait_group 1;" ::: "memory")

#define LDMX4(r0, r1, r2, r3, addr) \
    asm volatile("ldmatrix.sync.aligned.m8n8.x4.shared.b16 {%0,%1,%2,%3}, [%4];" \
        : "=r"(r0), "=r"(r1), "=r"(r2), "=r"(r3) : "r"(addr))

#define MMA16816(d, a, b0, b1) \
    asm volatile("mma.sync.aligned.m16n8k16.row.col.f32.bf16.bf16.f32 " \
        "{%0,%1,%2,%3}, {%4,%5,%6,%7}, {%8,%9}, {%0,%1,%2,%3};" \
        : "+f"((d)[0]), "+f"((d)[1]), "+f"((d)[2]), "+f"((d)[3]) \
        : "r"((a)[0]), "r"((a)[1]), "r"((a)[2]), "r"((a)[3]), "r"(b0), "r"(b1))

// ======================= prep kernels =======================================
__global__ void __launch_bounds__(256) ksplit(const float* __restrict__ X,
                                              __nv_bfloat16* __restrict__ H,
                                              __nv_bfloat16* __restrict__ L, int n)
{
    int i = (blockIdx.x * 256 + threadIdx.x) * 4;
    if (i >= n) return;
    float4 v = *(const float4*)(X + i);
    __nv_bfloat16 h0 = __float2bfloat16(v.x), h1 = __float2bfloat16(v.y);
    __nv_bfloat16 h2 = __float2bfloat16(v.z), h3 = __float2bfloat16(v.w);
    __nv_bfloat16 l0 = __float2bfloat16(v.x - __bfloat162float(h0));
    __nv_bfloat16 l1 = __float2bfloat16(v.y - __bfloat162float(h1));
    __nv_bfloat16 l2 = __float2bfloat16(v.z - __bfloat162float(h2));
    __nv_bfloat16 l3 = __float2bfloat16(v.w - __bfloat162float(h3));
    ((__nv_bfloat162*)(H + i))[0] = __nv_bfloat162(h0, h1);
    ((__nv_bfloat162*)(H + i))[1] = __nv_bfloat162(h2, h3);
    ((__nv_bfloat162*)(L + i))[0] = __nv_bfloat162(l0, l1);
    ((__nv_bfloat162*)(L + i))[1] = __nv_bfloat162(l2, l3);
}

// W[K,N] f32 -> H,L [N,K] bf16 (transpose + split)
__global__ void __launch_bounds__(256) ksplitT(const float* __restrict__ W,
                                               __nv_bfloat16* __restrict__ H,
                                               __nv_bfloat16* __restrict__ L,
                                               int K, int N)
{
    __shared__ float t[32][33];
    int n0 = blockIdx.x * 32, k0 = blockIdx.y * 32;
    int tx = threadIdx.x, ty = threadIdx.y;
    #pragma unroll
    for (int r = ty; r < 32; r += 8)
        t[r][tx] = W[(long)(k0 + r) * N + n0 + tx];
    __syncthreads();
    #pragma unroll
    for (int r = ty; r < 32; r += 8) {
        float v = t[tx][r];
        __nv_bfloat16 h = __float2bfloat16(v);
        __nv_bfloat16 l = __float2bfloat16(v - __bfloat162float(h));
        long o = (long)(n0 + r) * K + k0 + tx;
        H[o] = h;
        L[o] = l;
    }
}

// ======================= path-bias precompute ===============================
__global__ void __launch_bounds__(256) pb_kernel(
    const int* __restrict__ traj, const int* __restrict__ distance,
    const float* __restrict__ path_emb, const float* __restrict__ path_pos,
    float* __restrict__ pb_out)
{
    __shared__ __align__(16) int stg[8][200];
    __shared__ __align__(16) float tile[32][132];
    const int tid = threadIdx.x, w = tid >> 5, lane = tid & 31;
    const long e0 = (long)blockIdx.x * 128;
    const int we0 = w * 16;

    float wl[4];
    #pragma unroll
    for (int l = 0; l < 4; l++) wl[l] = path_pos[l * HH + lane];

    const int4* src = (const int4*)(traj + (e0 + we0) * 12);
    ((int4*)stg[w])[lane] = src[lane];
    if (lane < 16) ((int4*)stg[w])[32 + lane] = src[32 + lane];
    int ddv = 0;
    if (lane < 16) ddv = distance[e0 + we0 + lane];
    __syncwarp();

    #pragma unroll 4
    for (int k = 0; k < 16; k++) {
        int dd = __shfl_sync(0xffffffffu, ddv, k);
        const int* tj = &stg[w][k * 12];
        float acc = 0.f;
        #pragma unroll
        for (int l = 0; l < 4; l++) {
            float s3 = path_emb[tj[3 * l + 0] * HH + lane]
                     + path_emb[tj[3 * l + 1] * HH + lane]
                     + path_emb[tj[3 * l + 2] * HH + lane];
            acc += wl[l] * s3;
        }
        tile[lane][we0 + k] = acc * __frcp_rn(fmaxf((float)dd, 1.f));
    }
    __syncthreads();

    const int row = tid >> 3;
    const int c0 = (tid & 7) * 16;
    const long b = e0 >> 12;
    const long ijo = e0 & 4095;
    float* orow = pb_out + ((b * HH + row) << 12) + ijo;
    #pragma unroll
    for (int k2 = 0; k2 < 4; k2++) {
        float4 v = *(float4*)&tile[row][c0 + k2 * 4];
        *(float4*)&orow[c0 + k2 * 4] = v;
    }
}

// ======================= mma.sync GEMM (bf16x3) =============================
// 128x128x32 tile, 8 warps, 3-stage cp.async pipeline, 1 barrier/iter.
// SMEM rows: 64B (32 bf16), XOR chunk swizzle chunk'=(chunk+(row>>1))&3.
// R10-proven ordering: prefetch BEFORE LDSM (keeps regs at 128, 2 CTAs/SM).
#define GTILEB 8192                    // 128 rows * 64B
#define GM_STAGEB (4 * GTILEB)         // 32768 (Ah,Al,Bh,Bl)
#define GM_SMEM (3 * GM_STAGEB)        // 98304

__device__ __forceinline__ int swofs(int r, int ch) {
    return r * 64 + (((ch + (r >> 1)) & 3) << 4);
}

__global__ void __launch_bounds__(256, 2) mma_gemm_kernel(
    const __nv_bfloat16* __restrict__ Ah, const __nv_bfloat16* __restrict__ Al,
    const __nv_bfloat16* __restrict__ Bh, const __nv_bfloat16* __restrict__ Bl,
    const float* __restrict__ bias, float* __restrict__ C, int Ncols)
{
    extern __shared__ char smem[];
    const uint32_t sb = smem_u32(smem);
    const int tid = threadIdx.x, wid = tid >> 5, lane = tid & 31;
    const int nT = blockIdx.x, mT = blockIdx.y;
    const int wm = wid >> 1;
    const int wn = wid & 1;

    const __nv_bfloat16* srcA_h = Ah + (long)(mT * 128) * DD;
    const __nv_bfloat16* srcA_l = Al + (long)(mT * 128) * DD;
    const __nv_bfloat16* srcB_h = Bh + (long)(nT * 128) * DD;
    const __nv_bfloat16* srcB_l = Bl + (long)(nT * 128) * DD;

    float acc[2][8][4];
    #pragma unroll
    for (int s = 0; s < 2; s++)
        #pragma unroll
        for (int f = 0; f < 8; f++)
            #pragma unroll
            for (int x = 0; x < 4; x++) acc[s][f][x] = 0.f;

    auto load_stage = [&](int st, int k0) {
        uint32_t sbase = sb + st * GM_STAGEB;
        #pragma unroll
        for (int i = 0; i < 8; i++) {
            int idx = ((i & 1) << 8) + tid;
            int row = idx >> 2, ch = idx & 3;
            const __nv_bfloat16* src;
            switch (i >> 1) {
                case 0: src = srcA_h; break;
                case 1: src = srcA_l; break;
                case 2: src = srcB_h; break;
                default: src = srcB_l; break;
            }
            src += (long)row * DD + k0 + ch * 8;
            uint32_t dst = sbase + (i >> 1) * GTILEB + swofs(row, ch);
            CPASYNC16(dst, src);
        }
        CPCOMMIT();
    };

    load_stage(0, 0);
    load_stage(1, 32);

    const int arow = wm * 32 + (lane & 15);
    const int chq = lane >> 4;                     // 0 or 1

    for (int c = 0; c < 24; c++) {
        CPWAIT1();
        __syncthreads();
        if (c + 2 < 24) load_stage((c + 2) % 3, (c + 2) * 32);
        else CPCOMMIT();                            // keep wait depth uniform

        uint32_t st = sb + (c % 3) * GM_STAGEB;
        uint32_t sAh = st, sAl = st + GTILEB, sBh = st + 2 * GTILEB, sBl = st + 3 * GTILEB;

        #pragma unroll
        for (int kk = 0; kk < 2; kk++) {
            const int ch = kk * 2 + chq;
            uint32_t ah[2][4], al[2][4], bh[4][4], bl[4][4];
            LDMX4(ah[0][0], ah[0][1], ah[0][2], ah[0][3], sAh + swofs(arow, ch));
            LDMX4(ah[1][0], ah[1][1], ah[1][2], ah[1][3], sAh + swofs(arow + 16, ch));
            LDMX4(al[0][0], al[0][1], al[0][2], al[0][3], sAl + swofs(arow, ch));
            LDMX4(al[1][0], al[1][1], al[1][2], al[1][3], sAl + swofs(arow + 16, ch));
            #pragma unroll
            for (int g = 0; g < 4; g++) {
                int brow = wn * 64 + g * 16 + (lane & 15);
                LDMX4(bh[g][0], bh[g][1], bh[g][2], bh[g][3], sBh + swofs(brow, ch));
                LDMX4(bl[g][0], bl[g][1], bl[g][2], bl[g][3], sBl + swofs(brow, ch));
            }
            #pragma unroll
            for (int s = 0; s < 2; s++)
                #pragma unroll
                for (int f = 0; f < 8; f++) {
                    int g = f >> 1, p = f & 1;
                    MMA16816(acc[s][f], ah[s], bh[g][p], bh[g][p + 2]);
                    MMA16816(acc[s][f], ah[s], bl[g][p], bl[g][p + 2]);
                    MMA16816(acc[s][f], al[s], bh[g][p], bh[g][p + 2]);
                }
        }
    }

    #pragma unroll
    for (int s = 0; s < 2; s++) {
        int r0 = mT * 128 + wm * 32 + s * 16 + (lane >> 2);
        #pragma unroll
        for (int f = 0; f < 8; f++) {
            int col = nT * 128 + wn * 64 + f * 8 + (lane & 3) * 2;
            float b0 = bias[col], b1 = bias[col + 1];
            float2 v0 = make_float2(acc[s][f][0] + b0, acc[s][f][1] + b1);
            float2 v1 = make_float2(acc[s][f][2] + b0, acc[s][f][3] + b1);
            *(float2*)&C[(long)r0 * Ncols + col] = v0;
            *(float2*)&C[(long)(r0 + 8) * Ncols + col] = v1;
        }
    }
}

// ---------------- fused attention: one CTA per (b,h) ------------------------
// qbe rows padded to 33 floats, qbd to 41 (bank-conflict-free for the 8
// stride-2 row accesses in phase 6: 66 mod 32 = 2, 82 mod 32 = 18).
#define QBE_S 33
#define QBD_S 41
#define OFF_SQ   0        /* 1600 */
#define OFF_SK   1600     /* 1600 */
#define OFF_SV   3200     /* 1600 */
#define OFF_QBE  4800     /* 64*33 = 2112 */
#define OFF_QBD  6912     /* 64*41 = 2624 */
#define OFF_KBE  9536     /* 2048 */
#define OFF_KBD  11584    /* 2560 */
#define OFF_VE   9536     /* 800 overlay */
#define OFF_VD   11584    /* 1000 overlay */
#define OFF_SA   14144    /* 64*65 = 4160 */
#define OFF_EQE  14144    /* overlays SA during phase 2 */
#define OFF_EKE  14944
#define OFF_EQD  15744
#define OFF_EKD  16744    /* ends 17744 < 18304 */
#define OFF_STR  18304
#define OFF_STC  18368
#define OFF_SMB  18432
#define SMEM_FLOATS 18496
#define SMEM_BYTES  (SMEM_FLOATS * 4)   /* 73984 -> 3 CTAs/SM */

__global__ void __launch_bounds__(256, 3) attn_kernel(
    const float* __restrict__ qkv,
    const int* __restrict__ distance,
    const int* __restrict__ conn,
    const float* __restrict__ pb,
    const unsigned char* __restrict__ mask,
    const float* __restrict__ eq_t, const float* __restrict__ ek_t,
    const float* __restrict__ dq_t, const float* __restrict__ dk_t,
    const float* __restrict__ ev_t, const float* __restrict__ dv_t,
    const float* __restrict__ toep_r, const float* __restrict__ toep_c,
    __nv_bfloat16* __restrict__ zh, __nv_bfloat16* __restrict__ zl)
{
    extern __shared__ float sm[];
    float* sq  = sm + OFF_SQ;
    float* sk  = sm + OFF_SK;
    float* sv  = sm + OFF_SV;
    float* qbe = sm + OFF_QBE;
    float* qbd = sm + OFF_QBD;
    float* kbe = sm + OFF_KBE;
    float* kbd = sm + OFF_KBD;
    float* ve  = sm + OFF_VE;
    float* vd  = sm + OFF_VD;
    float* sa  = sm + OFF_SA;
    float* eqe = sm + OFF_EQE;
    float* eke = sm + OFF_EKE;
    float* eqd = sm + OFF_EQD;
    float* ekd = sm + OFF_EKD;
    float* str = sm + OFF_STR;
    float* stc = sm + OFF_STC;
    float* smb = sm + OFF_SMB;

    const int h = blockIdx.x;
    const int b = blockIdx.y;
    const int tid = threadIdx.x;
    const int warp = tid >> 5, lane = tid & 31;

    // ---- phase 1: loads ----
    for (int idx = tid; idx < NN * DKK; idx += 256) {
        int i = idx / DKK, d = idx % DKK;
        long base = (long)(b * NN + i) * NQKV + h * DKK + d;
        sq[i * 25 + d] = qkv[base];
        sk[i * 25 + d] = qkv[base + HH * DKK];
        sv[i * 25 + d] = qkv[base + 2 * HH * DKK];
    }
    for (int idx = tid; idx < TEE * DKK; idx += 256) {
        int t = idx / DKK, d = idx % DKK;
        long g = (long)(t * HH + h) * DKK + d;
        eqe[t * 25 + d] = eq_t[g];
        eke[t * 25 + d] = ek_t[g];
    }
    for (int idx = tid; idx < TDD * DKK; idx += 256) {
        int t = idx / DKK, d = idx % DKK;
        long g = (long)(t * HH + h) * DKK + d;
        eqd[t * 25 + d] = dq_t[g];
        ekd[t * 25 + d] = dk_t[g];
    }
    if (tid < NN) {
        str[tid] = toep_r[h * NN + tid];
        stc[tid] = toep_c[h * NN + tid];
        smb[tid] = mask[b * NN + tid] ? -1e30f : 0.f;
    }
    __syncthreads();

    // ---- phase 2a: qb tables (64x72 fused) ----
    {
        const int ip = tid >> 3, tg = tid & 7;
        const int i0 = ip * 2;
        float a0[9], a1[9];
        const float* tp[9];
        #pragma unroll
        for (int k = 0; k < 9; k++) {
            int t = tg * 9 + k;
            tp[k] = (t < TEE) ? (eke + t * 25) : (ekd + (t - TEE) * 25);
            a0[k] = 0.f; a1[k] = 0.f;
        }
        #pragma unroll 8
        for (int d = 0; d < DKK; d++) {
            float q0 = sq[i0 * 25 + d], q1 = sq[(i0 + 1) * 25 + d];
            #pragma unroll
            for (int k = 0; k < 9; k++) {
                float e = tp[k][d];
                a0[k] += q0 * e;
                a1[k] += q1 * e;
            }
        }
        #pragma unroll
        for (int k = 0; k < 9; k++) {
            int t = tg * 9 + k;
            if (t < TEE) {
                qbe[i0 * QBE_S + t] = a0[k];
                qbe[(i0 + 1) * QBE_S + t] = a1[k];
            } else {
                qbd[i0 * QBD_S + t - TEE] = a0[k];
                qbd[(i0 + 1) * QBD_S + t - TEE] = a1[k];
            }
        }
    }
    // ---- phase 2b: kb tables (72x64 fused) ----
    if (tid < 192) {
        const int tt = tid >> 3, jg = tid & 7;
        float ac[3][8];
        const float* ep[3];
        #pragma unroll
        for (int c = 0; c < 3; c++) {
            int t = tt * 3 + c;
            ep[c] = (t < TEE) ? (eqe + t * 25) : (eqd + (t - TEE) * 25);
            #pragma unroll
            for (int jj = 0; jj < 8; jj++) ac[c][jj] = 0.f;
        }
        #pragma unroll 8
        for (int d = 0; d < DKK; d++) {
            float e0 = ep[0][d], e1 = ep[1][d], e2 = ep[2][d];
            #pragma unroll
            for (int jj = 0; jj < 8; jj++) {
                float kv = sk[(jg + 8 * jj) * 25 + d];
                ac[0][jj] += e0 * kv;
                ac[1][jj] += e1 * kv;
                ac[2][jj] += e2 * kv;
            }
        }
        #pragma unroll
        for (int c = 0; c < 3; c++) {
            int t = tt * 3 + c;
            #pragma unroll
            for (int jj = 0; jj < 8; jj++) {
                int j = jg + 8 * jj;
                if (t < TEE) kbe[t * 64 + j] = ac[c][jj];
                else         kbd[(t - TEE) * 64 + j] = ac[c][jj];
            }
        }
    }
    __syncthreads();

    // ---- phase 3: gathers + path bias -> sa, (warp,lane) layout ------------
    const long base_bij = (long)b * (NN * NN);
    const float* pbh = pb + (((long)(b * HH + h)) << 12);
    unsigned int cd[8];
    #pragma unroll
    for (int r = 0; r < 8; r++) {
        int i = warp + 8 * r;
        int c0 = conn[base_bij + i * 64 + lane];
        int d0 = distance[base_bij + i * 64 + lane];
        int c1 = conn[base_bij + i * 64 + 32 + lane];
        int d1 = distance[base_bij + i * 64 + 32 + lane];
        cd[r] = (unsigned)c0 | ((unsigned)d0 << 8) | ((unsigned)c1 << 16) | ((unsigned)d1 << 24);
        sa[i * 65 + lane] = qbe[i * QBE_S + c0] + kbe[c0 * 64 + lane]
                          + qbd[i * QBD_S + d0] + kbd[d0 * 64 + lane]
                          + pbh[i * 64 + lane];
        sa[i * 65 + 32 + lane] = qbe[i * QBE_S + c1] + kbe[c1 * 64 + 32 + lane]
                               + qbd[i * QBD_S + d1] + kbd[d1 * 64 + 32 + lane]
                               + pbh[i * 64 + 32 + lane];
    }
    __syncthreads();

    // ---- phase 4: QK dot (4i x 4j tile); zero accumulators; load Ve/Vd -----
    const float scale = 0.2041241452319315f;
    {
        const int ti = tid >> 4, tj = tid & 15;
        float acc[4][4];
        #pragma unroll
        for (int ii = 0; ii < 4; ii++)
            #pragma unroll
            for (int jj = 0; jj < 4; jj++) acc[ii][jj] = 0.f;
        #pragma unroll 8
        for (int d = 0; d < DKK; d++) {
            float qa[4], kv[4];
            #pragma unroll
            for (int ii = 0; ii < 4; ii++) qa[ii] = sq[(ti * 4 + ii) * 25 + d];
            #pragma unroll
            for (int jj = 0; jj < 4; jj++) kv[jj] = sk[(tj + 16 * jj) * 25 + d];
            #pragma unroll
            for (int ii = 0; ii < 4; ii++)
                #pragma unroll
                for (int jj = 0; jj < 4; jj++) acc[ii][jj] += qa[ii] * kv[jj];
        }
        #pragma unroll
        for (int ii = 0; ii < 4; ii++) {
            int i = ti * 4 + ii;
            #pragma unroll
            for (int jj = 0; jj < 4; jj++) {
                int j = tj + 16 * jj;
                sa[i * 65 + j] = (sa[i * 65 + j] + acc[ii][jj]) * scale + smb[j];
            }
        }
    }
    for (int idx = tid; idx < NN * QBE_S; idx += 256) qbe[idx] = 0.f;
    for (int idx = tid; idx < NN * QBD_S; idx += 256) qbd[idx] = 0.f;
    for (int idx = tid; idx < TEE * DKK; idx += 256) {
        int t = idx / DKK, d = idx % DKK;
        ve[t * 25 + d] = ev_t[(long)(t * HH + h) * DKK + d];
    }
    for (int idx = tid; idx < TDD * DKK; idx += 256) {
        int t = idx / DKK, d = idx % DKK;
        vd[t * 25 + d] = dv_t[(long)(t * HH + h) * DKK + d];
    }
    __syncthreads();

    // ---- phase 5: softmax + toeplitz + type scatter (bins from registers) --
    #pragma unroll
    for (int r = 0; r < 8; r++) {
        int i = warp + 8 * r;
        int c0v = cd[r] & 0xff, d0v = (cd[r] >> 8) & 0xff;
        int c1v = (cd[r] >> 16) & 0xff, d1v = cd[r] >> 24;
        float v0 = sa[i * 65 + lane];
        float v1 = sa[i * 65 + 32 + lane];
        float m = fmaxf(v0, v1);
        #pragma unroll
        for (int o = 16; o > 0; o >>= 1) m = fmaxf(m, __shfl_xor_sync(0xffffffffu, m, o));
        float e0 = __expf(v0 - m);
        float e1 = __expf(v1 - m);
        float s = e0 + e1;
        #pragma unroll
        for (int o = 16; o > 0; o >>= 1) s += __shfl_xor_sync(0xffffffffu, s, o);
        float inv = __frcp_rn(s);
        {
            int j = lane;
            float t = (j >= i) ? str[j - i] : stc[i - j];
            float av = e0 * inv * t;
            sa[i * 65 + j] = av;
            atomicAdd(&qbe[i * QBE_S + c0v], av);
            atomicAdd(&qbd[i * QBD_S + d0v], av);
        }
        {
            int j = lane + 32;
            float t = (j >= i) ? str[j - i] : stc[i - j];
            float av = e1 * inv * t;
            sa[i * 65 + j] = av;
            atomicAdd(&qbe[i * QBE_S + c1v], av);
            atomicAdd(&qbd[i * QBD_S + d1v], av);
        }
    }
    __syncthreads();

    // ---- phase 6: z = a@v + s_e@Ve + s_d@Vd -> split bf16 output -----------
    if (tid < 128) {
        const int ip = tid >> 2, dg = tid & 3;
        const int i0 = ip * 2, d0 = dg * 6;
        float acc[2][6];
        #pragma unroll
        for (int a = 0; a < 2; a++)
            #pragma unroll
            for (int x = 0; x < 6; x++) acc[a][x] = 0.f;
        #pragma unroll 4
        for (int j = 0; j < NN; j++) {
            float a0 = sa[i0 * 65 + j], a1 = sa[(i0 + 1) * 65 + j];
            #pragma unroll
            for (int x = 0; x < 6; x++) {
                float v = sv[j * 25 + d0 + x];
                acc[0][x] += a0 * v;
                acc[1][x] += a1 * v;
            }
        }
        #pragma unroll 4
        for (int t = 0; t < TEE; t++) {
            float a0 = qbe[i0 * QBE_S + t], a1 = qbe[(i0 + 1) * QBE_S + t];
            #pragma unroll
            for (int x = 0; x < 6; x++) {
                float v = ve[t * 25 + d0 + x];
                acc[0][x] += a0 * v;
                acc[1][x] += a1 * v;
            }
        }
        #pragma unroll 4
        for (int t = 0; t < TDD; t++) {
            float a0 = qbd[i0 * QBD_S + t], a1 = qbd[(i0 + 1) * QBD_S + t];
            #pragma unroll
            for (int x = 0; x < 6; x++) {
                float v = vd[t * 25 + d0 + x];
                acc[0][x] += a0 * v;
                acc[1][x] += a1 * v;
            }
        }
        #pragma unroll
        for (int a = 0; a < 2; a++) {
            long off = (long)(b * NN + i0 + a) * DD + h * DKK + d0;
            #pragma unroll
            for (int x = 0; x < 6; x++) {
                float v = acc[a][x];
                __nv_bfloat16 hi = __float2bfloat16(v);
                __nv_bfloat16 lo = __float2bfloat16(v - __bfloat162float(hi));
                zh[off + x] = hi;
                zl[off + x] = lo;
            }
        }
    }
}

// ---------------- host launch ------------------------------------------------
extern "C" void kernel_launch(void* const* d_in, const int* in_sizes, int n_in,
                              void* d_out, int out_size)
{
    const float* node  = (const float*)d_in[0];
    const int*   dist  = (const int*)d_in[1];
    const int*   conn  = (const int*)d_in[2];
    const int*   traj  = (const int*)d_in[3];
    const unsigned char* mask = (const unsigned char*)d_in[4];
    const float* W_qkv = (const float*)d_in[5];
    const float* b_qkv = (const float*)d_in[6];
    const float* W_out = (const float*)d_in[7];
    const float* b_out = (const float*)d_in[8];
    const float* eq_t  = (const float*)d_in[9];
    const float* ek_t  = (const float*)d_in[10];
    const float* dq_t  = (const float*)d_in[11];
    const float* dk_t  = (const float*)d_in[12];
    const float* pemb  = (const float*)d_in[13];
    const float* ppw   = (const float*)d_in[14];
    const float* ev_t  = (const float*)d_in[15];
    const float* dv_t  = (const float*)d_in[16];
    const float* tr    = (const float*)d_in[17];
    const float* tc    = (const float*)d_in[18];
    float* out = (float*)d_out;

    float *qkv_s, *pb_s;
    __nv_bfloat16 *Ah, *Al, *Bh, *Bl;
    cudaGetSymbolAddress((void**)&qkv_s, g_qkv);
    cudaGetSymbolAddress((void**)&pb_s,  g_pb);
    cudaGetSymbolAddress((void**)&Ah, g_Ah);
    cudaGetSymbolAddress((void**)&Al, g_Al);
    cudaGetSymbolAddress((void**)&Bh, g_Bh);
    cudaGetSymbolAddress((void**)&Bl, g_Bl);

    cudaFuncSetAttribute(mma_gemm_kernel, cudaFuncAttributeMaxDynamicSharedMemorySize, GM_SMEM);
    cudaFuncSetAttribute(attn_kernel, cudaFuncAttributeMaxDynamicSharedMemorySize, SMEM_BYTES);

    const int nA = BB * NN * DD;   // 8192*768

    // path-bias precompute
    pb_kernel<<<(BB * NN * NN) / 128, 256>>>(traj, dist, pemb, ppw, pb_s);

    // QKV projection via mma.sync bf16x3
    ksplit<<<nA / 4 / 256, 256>>>(node, Ah, Al, nA);
    ksplitT<<<dim3(NQKV / 32, DD / 32), dim3(32, 8)>>>(W_qkv, Bh, Bl, DD, NQKV);
    mma_gemm_kernel<<<dim3(NQKV / 128, (BB * NN) / 128), 256, GM_SMEM>>>(
        Ah, Al, Bh, Bl, b_qkv, qkv_s, NQKV);

    // fused attention -> writes z directly as split bf16 into Ah/Al
    attn_kernel<<<dim3(HH, BB), 256, SMEM_BYTES>>>(
        qkv_s, dist, conn, pb_s, mask,
        eq_t, ek_t, dq_t, dk_t, ev_t, dv_t, tr, tc, Ah, Al);

    // output projection via mma.sync bf16x3 (no ksplit pass needed)
    ksplitT<<<dim3(DD / 32, DD / 32), dim3(32, 8)>>>(W_out, Bh, Bl, DD, DD);
    mma_gemm_kernel<<<dim3(DD / 128, (BB * NN) / 128), 256, GM_SMEM>>>(
        Ah, Al, Bh, Bl, b_out, out, DD);
}